// round 5
// baseline (speedup 1.0000x reference)
#include <cuda_runtime.h>

// Problem shape fixed by setup_inputs(): x = (2, 4, 8, 256, 256) float32.
#define DD   8
#define HH   256
#define WW   256
#define NBC  8
#define HWsz 65536
#define DHWs 524288                  // 2^19
#define HT   16                      // h-rows per block tile
#define NTIL (HH / HT)               // 16
#define MAIN_BLOCKS (NBC * 6 * NTIL) // 768 (interior d = 1..6)
#define COPY_BLOCKS (NBC * 2 * NTIL) // 256 (d = 0, 7: pure defaults)

#define MAX_SHIFT 0.6f
#define BONUS     10.0f

// One Newton step. Returns 0 = moved, 1 = converged (valid), 2 = invalid.
__device__ __forceinline__ int quad_step(
    float c000, float pxm, float pxp, float pym, float pyp, float psm, float psp,
    float e011, float e01m, float e0m1, float e0mm,
    float e101, float e10m, float em01, float em0m,
    float e110, float e1m0, float em10, float emm0,
    int& dc, int& hc, int& wc,
    float& shx, float& shy, float& shs, float& gds)
{
    float gx = 0.5f * (pxp - pxm);
    float gy = 0.5f * (pyp - pym);
    float gs = 0.5f * (psp - psm);
    float dxx = pxp - 2.0f * c000 + pxm;
    float dyy = pyp - 2.0f * c000 + pym;
    float dss = psp - 2.0f * c000 + psm;
    float dxy = 0.25f * (e011 - e01m - e0m1 + e0mm);
    float dxs = 0.25f * (e101 - e10m - em01 + em0m);
    float dys = 0.25f * (e110 - e1m0 - em10 + emm0);

    float cf00 = dyy * dss - dys * dys;
    float cf01 = dxy * dss - dys * dxs;
    float cf02 = dxy * dys - dyy * dxs;
    float det  = dxx * cf00 - dxy * cf01 + dxs * cf02;
    if (!(fabsf(det) > 0.0f)) return 2;

    float r0 = -gx, r1 = -gy, r2 = -gs;
    float sx = (r0 * cf00 - dxy * (r1 * dss - dys * r2) + dxs * (r1 * dys - dyy * r2)) / det;
    float sy = (dxx * (r1 * dss - dys * r2) - r0 * cf01 + dxs * (dxy * r2 - r1 * dxs)) / det;
    float ss = (dxx * (dyy * r2 - r1 * dys) - dxy * (dxy * r2 - r1 * dxs) + r0 * cf02) / det;

    shx = sx; shy = sy; shs = ss;
    gds = gx * sx + gy * sy + gs * ss;

    int mvx = (sx > MAX_SHIFT) ? 1 : ((sx < -MAX_SHIFT) ? -1 : 0);
    int nw = wc + mvx;
    if (nw < 1 || nw > WW - 2) return 2;
    wc = nw;
    int mvy = (sy > MAX_SHIFT) ? 1 : ((sy < -MAX_SHIFT) ? -1 : 0);
    int nh = hc + mvy;
    if (nh < 1 || nh > HH - 2) return 2;
    hc = nh;
    int mvs = (ss > MAX_SHIFT) ? 1 : ((ss < -MAX_SHIFT) ? -1 : 0);
    int nd = dc + mvs;
    if (nd < 1 || nd > DD - 2) return 2;
    dc = nd;

    return ((mvx | mvy | mvs) == 0) ? 1 : 0;
}

__global__ __launch_bounds__(128)
void iqi3d_kernel(const float* __restrict__ x, float* __restrict__ out)
{
    const int tid = threadIdx.x;
    const int blk = blockIdx.x;
    const int lane = tid & 31;

    if (blk < MAIN_BLOCKS) {
        // =========== phase 1: mask + defaults + shared-list append ===========
        const int t  = blk & (NTIL - 1);
        const int q  = blk >> 4;
        const int d  = (q % 6) + 1;          // 1..6
        const int bc = q / 6;
        const int h0 = t * HT;

        const float* __restrict__ xb  = x + (size_t)bc * DHWs;
        const float2* __restrict__ xb2 = (const float2*)xb;
        const int w2 = tid << 1;

        __shared__ float sfull[2][WW];
        __shared__ unsigned short slist[1024];  // strict-maxima pack bound for 16x256
        __shared__ int scount;

        if (tid == 0) scount = 0;

        const int baseidx = d * (HWsz / 2) + tid;

        float2 A0, A1, A2, B0, B1, B2, C0, C1, C2, N0, N1, N2;
        {
            int hm = h0 - 1; if (hm < 0) hm = 0;
            A0 = xb2[baseidx - (HWsz / 2) + hm * (WW / 2)];
            A1 = xb2[baseidx               + hm * (WW / 2)];
            A2 = xb2[baseidx + (HWsz / 2) + hm * (WW / 2)];
            B0 = xb2[baseidx - (HWsz / 2) + h0 * (WW / 2)];
            B1 = xb2[baseidx               + h0 * (WW / 2)];
            B2 = xb2[baseidx + (HWsz / 2) + h0 * (WW / 2)];
            // C for row 0: h0 + 1 (always <= 255 since h0 <= 240)
            C0 = xb2[baseidx - (HWsz / 2) + (h0 + 1) * (WW / 2)];
            C1 = xb2[baseidx               + (h0 + 1) * (WW / 2)];
            C2 = xb2[baseidx + (HWsz / 2) + (h0 + 1) * (WW / 2)];
        }

        float* __restrict__ ob = out + (size_t)bc * 3 * DHWs + d * HWsz + h0 * WW;
        float* __restrict__ oy = out + (size_t)NBC * 3 * DHWs + (size_t)bc * DHWs
                                     + d * HWsz + h0 * WW;

        const float fw0 = (float)w2, fw1 = (float)(w2 + 1);
        const float fdd = (float)d;

#pragma unroll
        for (int r = 0; r < HT; ++r) {
            const int h = h0 + r;

            // compute this row's column maxes from the (A,B,C) window
            float ex0 = fmaxf(A0.x, A1.x); ex0 = fmaxf(ex0, A2.x);
            ex0 = fmaxf(ex0, B0.x); ex0 = fmaxf(ex0, B2.x);
            ex0 = fmaxf(ex0, C0.x); ex0 = fmaxf(ex0, C1.x); ex0 = fmaxf(ex0, C2.x);
            float ex1 = fmaxf(A0.y, A1.y); ex1 = fmaxf(ex1, A2.y);
            ex1 = fmaxf(ex1, B0.y); ex1 = fmaxf(ex1, B2.y);
            ex1 = fmaxf(ex1, C0.y); ex1 = fmaxf(ex1, C1.y); ex1 = fmaxf(ex1, C2.y);

            const float c0 = B1.x, c1 = B1.y;
            const float full0 = fmaxf(ex0, c0), full1 = fmaxf(ex1, c1);
            const int par = r & 1;
            *(float2*)&sfull[par][w2] = make_float2(full0, full1);

            // prefetch next row's C columns BEFORE the barrier (hidden by
            // the barrier wait + the whole mask/store body below)
            {
                int hn = h + 2; if (hn > HH - 1) hn = HH - 1;
                N0 = xb2[baseidx - (HWsz / 2) + hn * (WW / 2)];
                N1 = xb2[baseidx               + hn * (WW / 2)];
                N2 = xb2[baseidx + (HWsz / 2) + hn * (WW / 2)];
            }

            __syncthreads();
            int il = w2 - 1; if (il < 0) il = 0;
            int ir = w2 + 2; if (ir > WW - 1) ir = WW - 1;
            const float fl = sfull[par][il];
            const float fr = sfull[par][ir];

            const bool hin = (h >= 1) & (h <= HH - 2);
            const bool m0 = hin & (w2 >= 1)      & (c0 > fmaxf(ex0, fmaxf(fl, full1)));
            const bool m1 = hin & (w2 <= WW - 3) & (c1 > fmaxf(ex1, fmaxf(full0, fr)));

            // warp-aggregated append to the block-local list
            unsigned b0 = __ballot_sync(0xffffffffu, m0);
            unsigned b1 = __ballot_sync(0xffffffffu, m1);
            if (b0 | b1) {
                int n = __popc(b0) + __popc(b1);
                int leader = __ffs(b0 | b1) - 1;
                int base;
                if (lane == leader) base = atomicAdd(&scount, n);
                base = __shfl_sync(0xffffffffu, base, leader);
                unsigned lt = (lane == 31) ? 0x7fffffffu : ((1u << lane) - 1u);
                const int code = (r << 8) | w2;
                if (m0) slist[base + __popc(b0 & lt)] = (unsigned short)code;
                if (m1) slist[base + __popc(b0) + __popc(b1 & lt)] = (unsigned short)(code + 1);
            }

            // default outputs everywhere; phase 2 overwrites valid maxima
            const float fhh = (float)h;
            const int ro = r * WW + w2;
            *(float2*)&ob[0 * DHWs + ro] = make_float2(fdd, fdd);
            *(float2*)&ob[1 * DHWs + ro] = make_float2(fw0, fw1);
            *(float2*)&ob[2 * DHWs + ro] = make_float2(fhh, fhh);
            *(float2*)&oy[ro]            = make_float2(c0, c1);

            // roll the window
            A0 = B0; A1 = B1; A2 = B2;
            B0 = C0; B1 = C1; B2 = C2;
            C0 = N0; C1 = N1; C2 = N2;
        }

        // =========== phase 2: cooperative refine over compacted list ===========
        __syncthreads();
        const int cnt = scount;
#pragma unroll 1
        for (int i = tid; i < cnt; i += 128) {
            const int code = slist[i];
            const int r = code >> 8;
            const int w = code & 255;
            const int h = h0 + r;
            const int sp = d * HWsz + h * WW + w;

            int dc = d, hc = h, wc = w;
            float shx = 0.f, shy = 0.f, shs = 0.f, gds = 0.f;
            int st = 0;

#pragma unroll 1
            for (int it = 0; (it < 5) && (st == 0); ++it) {
                int ds_ = min(max(dc, 1), DD - 2);
                int hs_ = min(max(hc, 1), HH - 2);
                int ws_ = min(max(wc, 1), WW - 2);
                const float* p = xb + ds_ * HWsz + hs_ * WW + ws_;
                st = quad_step(p[0],
                    p[-1], p[1], p[-WW], p[WW], p[-HWsz], p[HWsz],
                    p[WW + 1], p[WW - 1], p[-WW + 1], p[-WW - 1],
                    p[HWsz + 1], p[HWsz - 1], p[-HWsz + 1], p[-HWsz - 1],
                    p[HWsz + WW], p[HWsz - WW], p[-HWsz + WW], p[-HWsz - WW],
                    dc, hc, wc, shx, shy, shs, gds);
            }

            bool valid = (st != 2)
                       && (fabsf(shx) <= 1.5f) && (fabsf(shy) <= 1.5f) && (fabsf(shs) <= 1.5f);
            if (valid) {
                const int cb = bc * 3 * DHWs;
                out[cb + 0 * DHWs + sp] = (float)dc + shs;
                out[cb + 1 * DHWs + sp] = (float)wc + shx;
                out[cb + 2 * DHWs + sp] = (float)hc + shy;
                out[(size_t)NBC * 3 * DHWs + (size_t)bc * DHWs + sp] =
                    xb[sp] + (0.5f * gds + BONUS);
            }
        }
    } else {
        // ---------- copy path: d = 0 and d = 7 are pure defaults ----------
        const int blk2 = blk - MAIN_BLOCKS;
        const int t  = blk2 & (NTIL - 1);
        const int q  = blk2 >> 4;
        const int d  = (q & 1) ? (DD - 1) : 0;
        const int bc = q >> 1;
        const int h0 = t * HT;

        const float4* __restrict__ xb4 =
            (const float4*)(x + (size_t)bc * DHWs + d * HWsz + h0 * WW);
        float* __restrict__ ob = out + (size_t)bc * 3 * DHWs + d * HWsz + h0 * WW;
        float* __restrict__ oy = out + (size_t)NBC * 3 * DHWs + (size_t)bc * DHWs
                                     + d * HWsz + h0 * WW;
        const float fdd = (float)d;

#pragma unroll
        for (int i = 0; i < (HT * WW / 4) / 128; ++i) {
            const int idx = i * 128 + tid;
            const int row = idx >> 6;
            const int wq  = (idx & 63) << 2;
            const float4 c = xb4[idx];
            const float fh = (float)(h0 + row);
            const int off = row * WW + wq;
            *(float4*)&ob[0 * DHWs + off] = make_float4(fdd, fdd, fdd, fdd);
            *(float4*)&ob[1 * DHWs + off] =
                make_float4((float)wq, (float)(wq + 1), (float)(wq + 2), (float)(wq + 3));
            *(float4*)&ob[2 * DHWs + off] = make_float4(fh, fh, fh, fh);
            *(float4*)&oy[off] = c;
        }
    }
}

extern "C" void kernel_launch(void* const* d_in, const int* in_sizes, int n_in,
                              void* d_out, int out_size)
{
    (void)in_sizes; (void)n_in; (void)out_size;
    const float* x = (const float*)d_in[0];
    float* out = (float*)d_out;
    iqi3d_kernel<<<MAIN_BLOCKS + COPY_BLOCKS, 128>>>(x, out);
}

// round 6
// speedup vs baseline: 1.0980x; 1.0980x over previous
#include <cuda_runtime.h>

// Problem shape fixed by setup_inputs(): x = (2, 4, 8, 256, 256) float32.
#define DD   8
#define HH   256
#define WW   256
#define NBC  8
#define HWsz 65536
#define DHWs 524288                  // 2^19
#define HT   8                       // h-rows per block tile
#define NTIL (HH / HT)               // 32
#define MAIN_BLOCKS (NBC * 6 * NTIL) // 1536 (interior d = 1..6)
#define COPY_BLOCKS (NBC * 2 * NTIL) // 512  (d = 0, 7: pure defaults)

#define MAX_SHIFT 0.6f
#define BONUS     10.0f

// One Newton step. Returns 0 = moved, 1 = converged (valid), 2 = invalid.
__device__ __forceinline__ int quad_step(
    float c000, float pxm, float pxp, float pym, float pyp, float psm, float psp,
    float e011, float e01m, float e0m1, float e0mm,
    float e101, float e10m, float em01, float em0m,
    float e110, float e1m0, float em10, float emm0,
    int& dc, int& hc, int& wc,
    float& shx, float& shy, float& shs, float& gds)
{
    float gx = 0.5f * (pxp - pxm);
    float gy = 0.5f * (pyp - pym);
    float gs = 0.5f * (psp - psm);
    float dxx = pxp - 2.0f * c000 + pxm;
    float dyy = pyp - 2.0f * c000 + pym;
    float dss = psp - 2.0f * c000 + psm;
    float dxy = 0.25f * (e011 - e01m - e0m1 + e0mm);
    float dxs = 0.25f * (e101 - e10m - em01 + em0m);
    float dys = 0.25f * (e110 - e1m0 - em10 + emm0);

    float cf00 = dyy * dss - dys * dys;
    float cf01 = dxy * dss - dys * dxs;
    float cf02 = dxy * dys - dyy * dxs;
    float det  = dxx * cf00 - dxy * cf01 + dxs * cf02;
    if (!(fabsf(det) > 0.0f)) return 2;

    float r0 = -gx, r1 = -gy, r2 = -gs;
    float sx = (r0 * cf00 - dxy * (r1 * dss - dys * r2) + dxs * (r1 * dys - dyy * r2)) / det;
    float sy = (dxx * (r1 * dss - dys * r2) - r0 * cf01 + dxs * (dxy * r2 - r1 * dxs)) / det;
    float ss = (dxx * (dyy * r2 - r1 * dys) - dxy * (dxy * r2 - r1 * dxs) + r0 * cf02) / det;

    shx = sx; shy = sy; shs = ss;
    gds = gx * sx + gy * sy + gs * ss;

    int mvx = (sx > MAX_SHIFT) ? 1 : ((sx < -MAX_SHIFT) ? -1 : 0);
    int nw = wc + mvx;
    if (nw < 1 || nw > WW - 2) return 2;
    wc = nw;
    int mvy = (sy > MAX_SHIFT) ? 1 : ((sy < -MAX_SHIFT) ? -1 : 0);
    int nh = hc + mvy;
    if (nh < 1 || nh > HH - 2) return 2;
    hc = nh;
    int mvs = (ss > MAX_SHIFT) ? 1 : ((ss < -MAX_SHIFT) ? -1 : 0);
    int nd = dc + mvs;
    if (nd < 1 || nd > DD - 2) return 2;
    dc = nd;

    return ((mvx | mvy | mvs) == 0) ? 1 : 0;
}

// 26-neighbor exclusive/inclusive column maxes from a 3-row window.
// RA = h-1 row, RB = h row (center), RC = h+1 row; each is [d-1, d, d+1].
__device__ __forceinline__ void colmax(
    const float2 RA[3], const float2 RB[3], const float2 RC[3],
    float& ex0, float& ex1, float& full0, float& full1)
{
    ex0 = fmaxf(RA[0].x, RA[1].x); ex0 = fmaxf(ex0, RA[2].x);
    ex0 = fmaxf(ex0, RB[0].x); ex0 = fmaxf(ex0, RB[2].x);
    ex0 = fmaxf(ex0, RC[0].x); ex0 = fmaxf(ex0, RC[1].x); ex0 = fmaxf(ex0, RC[2].x);
    ex1 = fmaxf(RA[0].y, RA[1].y); ex1 = fmaxf(ex1, RA[2].y);
    ex1 = fmaxf(ex1, RB[0].y); ex1 = fmaxf(ex1, RB[2].y);
    ex1 = fmaxf(ex1, RC[0].y); ex1 = fmaxf(ex1, RC[1].y); ex1 = fmaxf(ex1, RC[2].y);
    full0 = fmaxf(ex0, RB[1].x);
    full1 = fmaxf(ex1, RB[1].y);
}

__global__ __launch_bounds__(128)
void iqi3d_kernel(const float* __restrict__ x, float* __restrict__ out)
{
    const int tid = threadIdx.x;
    const int blk = blockIdx.x;
    const int lane = tid & 31;

    if (blk < MAIN_BLOCKS) {
        // =========== phase 1: mask + defaults + shared-list append ===========
        const int t  = blk & (NTIL - 1);
        const int q  = blk >> 5;
        const int d  = (q % 6) + 1;          // 1..6
        const int bc = q / 6;
        const int h0 = t * HT;

        const float* __restrict__ xb  = x + (size_t)bc * DHWs;
        const float2* __restrict__ xb2 = (const float2*)xb;
        const int w2 = tid << 1;

        __shared__ float sfull[2][2][WW];     // [iter parity][row in pair][w]
        __shared__ unsigned short slist[512]; // strict-maxima bound for 8x256
        __shared__ int scount;

        if (tid == 0) scount = 0;

        const int baseidx = d * (HWsz / 2) + tid;

        // register window: R0=h-1, R1=h, R2=h+1, R3=h+2 (each [d-1,d,d+1])
        float2 R0[3], R1[3], R2[3], R3[3], N0[3], N1[3];
        {
            int hm = h0 - 1; if (hm < 0) hm = 0;
#pragma unroll
            for (int dd = 0; dd < 3; ++dd) {
                const int off = baseidx + (dd - 1) * (HWsz / 2);
                R0[dd] = xb2[off + hm * 128];
                R1[dd] = xb2[off + h0 * 128];
                R2[dd] = xb2[off + (h0 + 1) * 128];
                R3[dd] = xb2[off + (h0 + 2) * 128];
            }
        }

        float* __restrict__ ob = out + (size_t)bc * 3 * DHWs + d * HWsz + h0 * WW;
        float* __restrict__ oy = out + (size_t)NBC * 3 * DHWs + (size_t)bc * DHWs
                                     + d * HWsz + h0 * WW;

        const float fw0 = (float)w2, fw1 = (float)(w2 + 1);
        const float fdd = (float)d;

#pragma unroll
        for (int it = 0; it < HT / 2; ++it) {
            const int r  = it << 1;
            const int h  = h0 + r;
            const int p  = it & 1;

            // column maxes for rows h (R0,R1,R2) and h+1 (R1,R2,R3)
            float exA0, exA1, fullA0, fullA1;
            float exB0, exB1, fullB0, fullB1;
            colmax(R0, R1, R2, exA0, exA1, fullA0, fullA1);
            colmax(R1, R2, R3, exB0, exB1, fullB0, fullB1);
            const float cA0 = R1[1].x, cA1 = R1[1].y;
            const float cB0 = R2[1].x, cB1 = R2[1].y;

            *(float2*)&sfull[p][0][w2] = make_float2(fullA0, fullA1);
            *(float2*)&sfull[p][1][w2] = make_float2(fullB0, fullB1);

            // prefetch the next two rows before the barrier
            if (it < HT / 2 - 1) {
                int hn0 = h + 3; if (hn0 > HH - 1) hn0 = HH - 1;
                int hn1 = h + 4; if (hn1 > HH - 1) hn1 = HH - 1;
#pragma unroll
                for (int dd = 0; dd < 3; ++dd) {
                    const int off = baseidx + (dd - 1) * (HWsz / 2);
                    N0[dd] = xb2[off + hn0 * 128];
                    N1[dd] = xb2[off + hn1 * 128];
                }
            }

            __syncthreads();
            int il = w2 - 1; if (il < 0) il = 0;
            int ir = w2 + 2; if (ir > WW - 1) ir = WW - 1;
            const float flA = sfull[p][0][il], frA = sfull[p][0][ir];
            const float flB = sfull[p][1][il], frB = sfull[p][1][ir];

            const bool hinA = (h >= 1) & (h <= HH - 2);
            const bool hinB = (h + 1 >= 1) & (h + 1 <= HH - 2);
            const bool win0 = (w2 >= 1), win1 = (w2 <= WW - 3);
            const bool mA0 = hinA & win0 & (cA0 > fmaxf(exA0, fmaxf(flA, fullA1)));
            const bool mA1 = hinA & win1 & (cA1 > fmaxf(exA1, fmaxf(fullA0, frA)));
            const bool mB0 = hinB & win0 & (cB0 > fmaxf(exB0, fmaxf(flB, fullB1)));
            const bool mB1 = hinB & win1 & (cB1 > fmaxf(exB1, fmaxf(fullB0, frB)));

            // warp-aggregated append: ONE atomic per warp per row pair
            unsigned a0 = __ballot_sync(0xffffffffu, mA0);
            unsigned a1 = __ballot_sync(0xffffffffu, mA1);
            unsigned b0 = __ballot_sync(0xffffffffu, mB0);
            unsigned b1 = __ballot_sync(0xffffffffu, mB1);
            if (a0 | a1 | b0 | b1) {
                int n = __popc(a0) + __popc(a1) + __popc(b0) + __popc(b1);
                int leader = __ffs(a0 | a1 | b0 | b1) - 1;
                int base;
                if (lane == leader) base = atomicAdd(&scount, n);
                base = __shfl_sync(0xffffffffu, base, leader);
                unsigned lt = (lane == 31) ? 0x7fffffffu : ((1u << lane) - 1u);
                const int codeA = (r << 8) | w2;
                const int codeB = ((r + 1) << 8) | w2;
                int o = base;
                if (mA0) slist[o + __popc(a0 & lt)] = (unsigned short)codeA;
                o += __popc(a0);
                if (mA1) slist[o + __popc(a1 & lt)] = (unsigned short)(codeA + 1);
                o += __popc(a1);
                if (mB0) slist[o + __popc(b0 & lt)] = (unsigned short)codeB;
                o += __popc(b0);
                if (mB1) slist[o + __popc(b1 & lt)] = (unsigned short)(codeB + 1);
            }

            // default outputs for both rows
            const int roA = r * WW + w2, roB = roA + WW;
            const float fhA = (float)h, fhB = (float)(h + 1);
            *(float2*)&ob[0 * DHWs + roA] = make_float2(fdd, fdd);
            *(float2*)&ob[1 * DHWs + roA] = make_float2(fw0, fw1);
            *(float2*)&ob[2 * DHWs + roA] = make_float2(fhA, fhA);
            *(float2*)&oy[roA]            = make_float2(cA0, cA1);
            *(float2*)&ob[0 * DHWs + roB] = make_float2(fdd, fdd);
            *(float2*)&ob[1 * DHWs + roB] = make_float2(fw0, fw1);
            *(float2*)&ob[2 * DHWs + roB] = make_float2(fhB, fhB);
            *(float2*)&oy[roB]            = make_float2(cB0, cB1);

            // roll the window by 2 rows
#pragma unroll
            for (int dd = 0; dd < 3; ++dd) {
                R0[dd] = R2[dd]; R1[dd] = R3[dd];
                R2[dd] = N0[dd]; R3[dd] = N1[dd];
            }
        }

        // =========== phase 2: cooperative refine over compacted list ===========
        __syncthreads();
        const int cnt = scount;
#pragma unroll 1
        for (int i = tid; i < cnt; i += 128) {
            const int code = slist[i];
            const int r = code >> 8;
            const int w = code & 255;
            const int h = h0 + r;
            const int sp = d * HWsz + h * WW + w;

            int dc = d, hc = h, wc = w;
            float shx = 0.f, shy = 0.f, shs = 0.f, gds = 0.f;
            int st = 0;

#pragma unroll 1
            for (int itn = 0; (itn < 5) && (st == 0); ++itn) {
                int ds_ = min(max(dc, 1), DD - 2);
                int hs_ = min(max(hc, 1), HH - 2);
                int ws_ = min(max(wc, 1), WW - 2);
                const float* pp = xb + ds_ * HWsz + hs_ * WW + ws_;
                st = quad_step(pp[0],
                    pp[-1], pp[1], pp[-WW], pp[WW], pp[-HWsz], pp[HWsz],
                    pp[WW + 1], pp[WW - 1], pp[-WW + 1], pp[-WW - 1],
                    pp[HWsz + 1], pp[HWsz - 1], pp[-HWsz + 1], pp[-HWsz - 1],
                    pp[HWsz + WW], pp[HWsz - WW], pp[-HWsz + WW], pp[-HWsz - WW],
                    dc, hc, wc, shx, shy, shs, gds);
            }

            bool valid = (st != 2)
                       && (fabsf(shx) <= 1.5f) && (fabsf(shy) <= 1.5f) && (fabsf(shs) <= 1.5f);
            if (valid) {
                const int cb = bc * 3 * DHWs;
                out[cb + 0 * DHWs + sp] = (float)dc + shs;
                out[cb + 1 * DHWs + sp] = (float)wc + shx;
                out[cb + 2 * DHWs + sp] = (float)hc + shy;
                out[(size_t)NBC * 3 * DHWs + (size_t)bc * DHWs + sp] =
                    xb[sp] + (0.5f * gds + BONUS);
            }
        }
    } else {
        // ---------- copy path: d = 0 and d = 7 are pure defaults ----------
        const int blk2 = blk - MAIN_BLOCKS;
        const int t  = blk2 & (NTIL - 1);
        const int q  = blk2 >> 5;
        const int d  = (q & 1) ? (DD - 1) : 0;
        const int bc = q >> 1;
        const int h0 = t * HT;

        const float4* __restrict__ xb4 =
            (const float4*)(x + (size_t)bc * DHWs + d * HWsz + h0 * WW);
        float* __restrict__ ob = out + (size_t)bc * 3 * DHWs + d * HWsz + h0 * WW;
        float* __restrict__ oy = out + (size_t)NBC * 3 * DHWs + (size_t)bc * DHWs
                                     + d * HWsz + h0 * WW;
        const float fdd = (float)d;

#pragma unroll
        for (int i = 0; i < (HT * WW / 4) / 128; ++i) {
            const int idx = i * 128 + tid;
            const int row = idx >> 6;
            const int wq  = (idx & 63) << 2;
            const float4 c = xb4[idx];
            const float fh = (float)(h0 + row);
            const int off = row * WW + wq;
            *(float4*)&ob[0 * DHWs + off] = make_float4(fdd, fdd, fdd, fdd);
            *(float4*)&ob[1 * DHWs + off] =
                make_float4((float)wq, (float)(wq + 1), (float)(wq + 2), (float)(wq + 3));
            *(float4*)&ob[2 * DHWs + off] = make_float4(fh, fh, fh, fh);
            *(float4*)&oy[off] = c;
        }
    }
}

extern "C" void kernel_launch(void* const* d_in, const int* in_sizes, int n_in,
                              void* d_out, int out_size)
{
    (void)in_sizes; (void)n_in; (void)out_size;
    const float* x = (const float*)d_in[0];
    float* out = (float*)d_out;
    iqi3d_kernel<<<MAIN_BLOCKS + COPY_BLOCKS, 128>>>(x, out);
}